// round 11
// baseline (speedup 1.0000x reference)
#include <cuda_runtime.h>
#include <cuda_bf16.h>
#include <math.h>
#include <stdint.h>

#define Bdim 128
#define Tdim 256
#define Adim 8
#define Hdim 1024
#define BT   (Bdim * Tdim)        // 32768
#define G3H  (3 * Hdim)           // 3072
#define KC   3072                 // concat K for split-bf16 GEMM
#define NCH  48                   // K chunks of 64 (xp gemm)
#define GCH  24                   // K chunks of 128 (gru)

// ---------------- device scratch ----------------
__device__ float g_xp[(size_t)BT * G3H];                 // [BT,3H] fp32
__device__ __nv_bfloat16 g_Axp[(size_t)BT * KC];         // [x1|x1|x2]
__device__ __nv_bfloat16 g_Bih[(size_t)G3H * KC];        // row n: [w1|w2|w1]
__device__ __nv_bfloat16 g_Bhh[(size_t)G3H * KC];        // row j=3i+g: [w1|w2|w1]
__device__ __nv_bfloat16 g_Ah[2][(size_t)Bdim * KC];     // [h1|h1|h2] ping-pong
__device__ unsigned g_bar_count;
__device__ unsigned g_bar_flag;

// ---------------- helpers ----------------
__device__ __forceinline__ uint32_t smem_to_u32(const void* p) {
    uint32_t a;
    asm("{ .reg .u64 t; cvta.to.shared.u64 t, %1; cvt.u32.u64 %0, t; }" : "=r"(a) : "l"(p));
    return a;
}
__device__ __forceinline__ void ldsm4(uint32_t* r, uint32_t a) {
    asm volatile("ldmatrix.sync.aligned.m8n8.x4.shared.b16 {%0,%1,%2,%3}, [%4];"
        : "=r"(r[0]), "=r"(r[1]), "=r"(r[2]), "=r"(r[3]) : "r"(a));
}
__device__ __forceinline__ void mma16816(float* d, const uint32_t* a, const uint32_t* b) {
    asm volatile("mma.sync.aligned.m16n8k16.row.col.f32.bf16.bf16.f32 "
        "{%0,%1,%2,%3}, {%4,%5,%6,%7}, {%8,%9}, {%0,%1,%2,%3};"
        : "+f"(d[0]), "+f"(d[1]), "+f"(d[2]), "+f"(d[3])
        : "r"(a[0]), "r"(a[1]), "r"(a[2]), "r"(a[3]), "r"(b[0]), "r"(b[1]));
}
#define CP_ASYNC16(d, s) asm volatile("cp.async.cg.shared.global [%0], [%1], 16;" :: "r"(d), "l"(s))
#define CP_COMMIT()      asm volatile("cp.async.commit_group;" ::: "memory")
#define CP_WAIT2()       asm volatile("cp.async.wait_group 2;" ::: "memory")
#define CP_WAIT4()       asm volatile("cp.async.wait_group 4;" ::: "memory")
#define CP_WAIT_ALL()    asm volatile("cp.async.wait_group 0;" ::: "memory")
#define SWZ(o) ((o) ^ (((o) >> 3) & 0x70))

// ---------------- kernel 1: proj + split  ([x1|x1|x2]) ------------------
__global__ __launch_bounds__(128) void proj_split(
    const float* __restrict__ actions, const float* __restrict__ fc_w,
    const float* __restrict__ fc_b)
{
    const int m = blockIdx.x, t = threadIdx.x;
    __shared__ float act[Adim];
    if (t < Adim) act[t] = actions[m * Adim + t];
    __syncthreads();
    const float a0 = act[0], a1 = act[1], a2 = act[2], a3 = act[3];
    const float a4 = act[4], a5 = act[5], a6 = act[6], a7 = act[7];
    __nv_bfloat16* dst = g_Axp + (size_t)m * KC;
#pragma unroll
    for (int j = 0; j < Hdim / 128; j++) {
        const int h = t + j * 128;
        const float4* wp = reinterpret_cast<const float4*>(fc_w + (size_t)h * Adim);
        const float4 w0 = wp[0], w1 = wp[1];
        float v = fc_b[h];
        v += a0 * w0.x + a1 * w0.y + a2 * w0.z + a3 * w0.w;
        v += a4 * w1.x + a5 * w1.y + a6 * w1.z + a7 * w1.w;
        v = fmaxf(v, 0.0f);
        const __nv_bfloat16 x1 = __float2bfloat16(v);
        const __nv_bfloat16 x2 = __float2bfloat16(v - __bfloat162float(x1));
        dst[h] = x1; dst[Hdim + h] = x1; dst[2 * Hdim + h] = x2;
    }
}

// ---------------- kernel 2: weight splits -------------------------------
__global__ __launch_bounds__(256) void split_w(
    const float* __restrict__ w_ih, const float* __restrict__ w_hh)
{
    const int bid = blockIdx.x;
    const float* src;
    __nv_bfloat16* dst;
    if (bid < G3H) {
        src = w_ih + (size_t)bid * Hdim;
        dst = g_Bih + (size_t)bid * KC;
    } else {
        const int j = bid - G3H, g = j % 3, i = j / 3;
        src = w_hh + (size_t)(g * Hdim + i) * Hdim;
        dst = g_Bhh + (size_t)j * KC;
    }
#pragma unroll
    for (int u = 0; u < Hdim / 256; u++) {
        const int k = threadIdx.x + u * 256;
        const float w = src[k];
        const __nv_bfloat16 w1 = __float2bfloat16(w);
        const __nv_bfloat16 w2 = __float2bfloat16(w - __bfloat162float(w1));
        dst[k] = w1; dst[Hdim + k] = w2; dst[2 * Hdim + k] = w1;
    }
}

// ---------------- kernel 3: split hidden + reset barrier ----------------
__global__ __launch_bounds__(256) void split_h0(const float* __restrict__ hidden)
{
    if (blockIdx.x == 0 && threadIdx.x == 0) { g_bar_count = 0; g_bar_flag = 0; }
    const int b = blockIdx.x;
    __nv_bfloat16* dst = g_Ah[0] + (size_t)b * KC;
    const float* src = hidden + (size_t)b * Hdim;
#pragma unroll
    for (int u = 0; u < Hdim / 256; u++) {
        const int k = threadIdx.x + u * 256;
        const float h = src[k];
        const __nv_bfloat16 h1 = __float2bfloat16(h);
        const __nv_bfloat16 h2 = __float2bfloat16(h - __bfloat162float(h1));
        dst[k] = h1; dst[Hdim + k] = h1; dst[2 * Hdim + k] = h2;
    }
}

// ---------------- kernel 4: xp GEMM via mma.sync (proven) ---------------
#define XP_STAGE 28672
#define XP_SMEM  (4 * XP_STAGE)

__global__ __launch_bounds__(256) void xp_mma(const float* __restrict__ b_ih)
{
    extern __shared__ char sm[];
    const uint32_t smb = smem_to_u32(sm);
    const int tid = threadIdx.x, lane = tid & 31, wid = tid >> 5;
    const int nb = blockIdx.x, mb = blockIdx.y;

    uint32_t sdst[7]; const char* gsrc[7];
#pragma unroll
    for (int u = 0; u < 7; u++) {
        const int sidx = tid + u * 256;
        if (sidx < 1024) {
            const int row = sidx >> 3, s8 = sidx & 7;
            sdst[u] = SWZ((uint32_t)(row * 128 + s8 * 16));
            gsrc[u] = (const char*)g_Axp + (size_t)(mb * 128 + row) * (KC * 2) + s8 * 16;
        } else {
            const int bx = sidx - 1024, row = bx >> 3, s8 = bx & 7;
            sdst[u] = 16384u + SWZ((uint32_t)(row * 128 + s8 * 16));
            gsrc[u] = (const char*)g_Bih + (size_t)(nb * 96 + row) * (KC * 2) + s8 * 16;
        }
    }
    auto prefetch = [&](int c) {
        if (c < NCH) {
            const uint32_t sb = smb + (uint32_t)(c & 3) * XP_STAGE;
            const size_t off = (size_t)c * 128;
#pragma unroll
            for (int u = 0; u < 7; u++) CP_ASYNC16(sb + sdst[u], gsrc[u] + off);
        }
        CP_COMMIT();
    };

    const int mrow0 = (wid & 3) * 32, nc0 = (wid >> 2) * 48;
    const uint32_t ar0 = mrow0 + (lane & 15), ar1 = ar0 + 16;
    const uint32_t aoff0 = ar0 * 128, amk0 = (ar0 & 7) << 4;
    const uint32_t aoff1 = ar1 * 128, amk1 = (ar1 & 7) << 4;
    const uint32_t akh = (uint32_t)(lane >> 4) * 16;
    uint32_t boff[3], bmk[3];
#pragma unroll
    for (int p = 0; p < 3; p++) {
        const uint32_t nr = nc0 + p * 16 + (lane >> 4) * 8 + (lane & 7);
        boff[p] = 16384u + nr * 128; bmk[p] = (nr & 7) << 4;
    }
    const uint32_t bkh = (uint32_t)((lane >> 3) & 1) * 16;

    float acc[2][6][4] = {};
    prefetch(0); prefetch(1); prefetch(2);
    for (int c = 0; c < NCH; c++) {
        CP_WAIT2();
        __syncthreads();
        prefetch(c + 3);
        const uint32_t sb = smb + (uint32_t)(c & 3) * XP_STAGE;
#pragma unroll
        for (int s = 0; s < 4; s++) {
            uint32_t a0[4], a1[4], b[12];
            const uint32_t cA = akh + s * 32, cB = bkh + s * 32;
            ldsm4(a0, sb + aoff0 + (cA ^ amk0));
            ldsm4(a1, sb + aoff1 + (cA ^ amk1));
#pragma unroll
            for (int p = 0; p < 3; p++) ldsm4(b + 4 * p, sb + boff[p] + (cB ^ bmk[p]));
#pragma unroll
            for (int nt = 0; nt < 6; nt++) {
                mma16816(acc[0][nt], a0, b + 2 * nt);
                mma16816(acc[1][nt], a1, b + 2 * nt);
            }
        }
    }

    const int q = lane & 3, r4 = lane >> 2;
#pragma unroll
    for (int mg = 0; mg < 2; mg++) {
        const int row = mb * 128 + mrow0 + mg * 16 + r4;
#pragma unroll
        for (int nt = 0; nt < 6; nt++) {
            const int col = nb * 96 + nc0 + nt * 8 + 2 * q;
            const float2 bias = *reinterpret_cast<const float2*>(b_ih + col);
            float2 v0, v1;
            v0.x = acc[mg][nt][0] + bias.x; v0.y = acc[mg][nt][1] + bias.y;
            v1.x = acc[mg][nt][2] + bias.x; v1.y = acc[mg][nt][3] + bias.y;
            *reinterpret_cast<float2*>(g_xp + (size_t)row * G3H + col) = v0;
            *reinterpret_cast<float2*>(g_xp + (size_t)(row + 8) * G3H + col) = v1;
        }
    }
}

// ---------------- kernel 5: persistent GRU, 512 thr, 6-stage pipe -------
// 128 CTAs (nb 0..31, mb 0..3). Tile 32x96, K=3072 in 24 chunks of 128.
// Stage = two 16KB halves: 32KB x 6 stages (192KB). 16 warps, 4-way s-split.
// B cp.asyncs for the next step's fill are issued BEFORE the device barrier
// (B is step-invariant); A parts + commits issued after. Group 0 of each
// step therefore contains B0..B4+A0 — wait_group accounting stays exact.
#define GR_STAGE 32768
#define GR_NST   6
#define GR_SMEM  (GR_NST * GR_STAGE)
#define NBLK 128

__global__ __launch_bounds__(512) void gru_persist(
    const float* __restrict__ hidden,
    const float* __restrict__ b_hh, float* __restrict__ out)
{
    extern __shared__ char sm[];
    const uint32_t smb = smem_to_u32(sm);
    const int tid = threadIdx.x, lane = tid & 31, wid = tid >> 5;
    const int kw = wid >> 2;                  // 0..3: sub-step pair
    const int q  = wid & 3;                   // quad within group
    const int nb = blockIdx.x, mb = blockIdx.y;
    const int b0 = mb * 32, i0 = nb * 32;

    // ---- step-invariant load addresses: 1 A seg + 3 B segs per thread ----
    uint32_t sdstA; size_t aoffA;
    uint32_t sdstB[3]; const char* bsrc[3];
    {
        const int h = tid >> 8, r = (tid & 255) >> 3, s8 = tid & 7;
        sdstA = (uint32_t)(h * 16384) + SWZ((uint32_t)(r * 128 + s8 * 16));
        aoffA = (size_t)(b0 + r) * (KC * 2) + h * 128 + s8 * 16;
    }
#pragma unroll
    for (int u = 0; u < 3; u++) {
        const int bx = tid + u * 512;         // 0..1535
        const int h = bx >= 768, rb = (bx - h * 768) >> 3, s8 = bx & 7;
        sdstB[u] = (uint32_t)(h * 16384 + 4096) + SWZ((uint32_t)(rb * 128 + s8 * 16));
        bsrc[u] = (const char*)g_Bhh + (size_t)(nb * 96 + rb) * (KC * 2) + h * 128 + s8 * 16;
    }

    const int mrow0 = (q & 1) * 16, nc0 = (q >> 1) * 48;
    const uint32_t ar = mrow0 + (lane & 15);
    const uint32_t aoff = ar * 128, amk = (ar & 7) << 4;
    const uint32_t akh = (uint32_t)(lane >> 4) * 16;
    uint32_t boff[3], bmk[3];
#pragma unroll
    for (int p = 0; p < 3; p++) {
        const uint32_t nr = nc0 + p * 16 + (lane >> 4) * 8 + (lane & 7);
        boff[p] = 4096u + nr * 128; bmk[p] = (nr & 7) << 4;
    }
    const uint32_t bkh = (uint32_t)((lane >> 3) & 1) * 16;

    // ---- step-invariant epilogue state: h and biases in regs ----
    float hv[2], bh0[2], bh1[2], bh2[2];
#pragma unroll
    for (int u = 0; u < 2; u++) {
        const int idx = tid + u * 512;
        const int b = b0 + (idx >> 5), i = i0 + (idx & 31);
        hv[u]  = hidden[(size_t)b * Hdim + i];
        bh0[u] = b_hh[i]; bh1[u] = b_hh[Hdim + i]; bh2[u] = b_hh[2 * Hdim + i];
    }

    auto issueB = [&](int c, int st) {
        const uint32_t sb = smb + (uint32_t)st * GR_STAGE;
        const size_t off = (size_t)c * 256;
#pragma unroll
        for (int u = 0; u < 3; u++) CP_ASYNC16(sb + sdstB[u], bsrc[u] + off);
    };

    // pre-issue B fill for step 0 (uncommitted)
#pragma unroll
    for (int c = 0; c < 5; c++) issueB(c, c);

    for (int t = 0; t < Tdim; t++) {
        const char* Ab = (const char*)g_Ah[t & 1];
        float acc[6][4] = {};

        // A fill + commits (B parts already issued pre-barrier)
#pragma unroll
        for (int c = 0; c < 5; c++) {
            const uint32_t sb = smb + (uint32_t)c * GR_STAGE;
            CP_ASYNC16(sb + sdstA, Ab + aoffA + (size_t)c * 256);
            CP_COMMIT();
        }

        int sc = 0;
        for (int c = 0; c < GCH; c++) {
            CP_WAIT4();
            __syncthreads();
            const int cp = c + 5;
            if (cp < GCH) {
                int sp = sc + 5; if (sp >= GR_NST) sp -= GR_NST;
                const uint32_t sb = smb + (uint32_t)sp * GR_STAGE;
                issueB(cp, sp);
                CP_ASYNC16(sb + sdstA, Ab + aoffA + (size_t)cp * 256);
            }
            CP_COMMIT();
            const uint32_t sb = smb + (uint32_t)sc * GR_STAGE;
#pragma unroll
            for (int s2 = 0; s2 < 2; s2++) {
                const int s = kw * 2 + s2;                // 0..7
                const uint32_t hb = (uint32_t)(s >> 2) * 16384;
                const int sl = s & 3;
                uint32_t a[4], b[12];
                const uint32_t cA = akh + sl * 32, cB = bkh + sl * 32;
                ldsm4(a, sb + hb + aoff + (cA ^ amk));
#pragma unroll
                for (int p = 0; p < 3; p++)
                    ldsm4(b + 4 * p, sb + hb + boff[p] + (cB ^ bmk[p]));
#pragma unroll
                for (int nt = 0; nt < 6; nt++) mma16816(acc[nt], a, b + 2 * nt);
            }
            sc++; if (sc == GR_NST) sc = 0;
        }
        CP_WAIT_ALL();

        // hoisted xp loads (latency hidden under the smem reduce)
        float xr[2], xz[2], xn[2];
#pragma unroll
        for (int u = 0; u < 2; u++) {
            const int idx = tid + u * 512;
            const int b = b0 + (idx >> 5), i = i0 + (idx & 31);
            const float* xpr = g_xp + ((size_t)b * Tdim + t) * G3H;
            xr[u] = xpr[i]; xz[u] = xpr[Hdim + i]; xn[u] = xpr[2 * Hdim + i];
        }

        // ---- reduce the four K-quarter partials via smem ----
        float* hp = reinterpret_cast<float*>(sm);  // 4 x [32][100] fp32
        __syncthreads();
        {
            float* hpk = hp + kw * 3200;
            const int q4 = lane & 3, r0 = mrow0 + (lane >> 2);
#pragma unroll
            for (int nt = 0; nt < 6; nt++) {
                const int cc = nc0 + nt * 8 + 2 * q4;
                hpk[r0 * 100 + cc]           = acc[nt][0];
                hpk[r0 * 100 + cc + 1]       = acc[nt][1];
                hpk[(r0 + 8) * 100 + cc]     = acc[nt][2];
                hpk[(r0 + 8) * 100 + cc + 1] = acc[nt][3];
            }
        }
        __syncthreads();

        __nv_bfloat16* Abase = g_Ah[(t & 1) ^ 1];
#pragma unroll
        for (int u = 0; u < 2; u++) {
            const int idx = tid + u * 512;
            const int bl = idx >> 5, il = idx & 31;
            const int b = b0 + bl, i = i0 + il;
            const int o = bl * 100 + 3 * il;
            const float hr = hp[o + 0] + hp[3200 + o + 0] + hp[6400 + o + 0] + hp[9600 + o + 0] + bh0[u];
            const float hz = hp[o + 1] + hp[3200 + o + 1] + hp[6400 + o + 1] + hp[9600 + o + 1] + bh1[u];
            const float hn = hp[o + 2] + hp[3200 + o + 2] + hp[6400 + o + 2] + hp[9600 + o + 2] + bh2[u];
            const float rg = 1.0f / (1.0f + expf(-(xr[u] + hr)));
            const float zg = 1.0f / (1.0f + expf(-(xz[u] + hz)));
            const float ng = tanhf(xn[u] + rg * hn);
            const float hnew = (1.0f - zg) * ng + zg * hv[u];
            hv[u] = hnew;
            out[((size_t)b * Tdim + t) * Hdim + i] = hnew;
            const __nv_bfloat16 h1 = __float2bfloat16(hnew);
            const __nv_bfloat16 h2 = __float2bfloat16(hnew - __bfloat162float(h1));
            __nv_bfloat16* An = Abase + (size_t)b * KC;
            An[i] = h1; An[Hdim + i] = h1; An[2 * Hdim + i] = h2;
        }
        __syncthreads();

        // ---- pre-issue next step's B fill (step-invariant, pre-barrier) ----
        if (t + 1 < Tdim) {
#pragma unroll
            for (int c = 0; c < 5; c++) issueB(c, c);
        }

        // ---- device-wide barrier ----
        if (tid == 0) {
            __threadfence();
            const unsigned prev = atomicAdd(&g_bar_count, 1u);
            if (prev == NBLK - 1) {
                g_bar_count = 0;
                __threadfence();
                atomicExch(&g_bar_flag, (unsigned)(t + 1));
            } else {
                while (atomicAdd(&g_bar_flag, 0u) < (unsigned)(t + 1))
                    __nanosleep(64);
            }
            __threadfence();
        }
        __syncthreads();
    }
}

// ---------------------------------------------------------------------------
extern "C" void kernel_launch(void* const* d_in, const int* in_sizes, int n_in,
                              void* d_out, int out_size)
{
    const float* actions = (const float*)d_in[0];
    const float* hidden  = (const float*)d_in[1];
    const float* fc_w    = (const float*)d_in[2];
    const float* fc_b    = (const float*)d_in[3];
    const float* w_ih    = (const float*)d_in[4];
    const float* w_hh    = (const float*)d_in[5];
    const float* b_ih    = (const float*)d_in[6];
    const float* b_hh    = (const float*)d_in[7];
    float* out = (float*)d_out;

    static bool attr_set = false;
    if (!attr_set) {
        cudaFuncSetAttribute(xp_mma, cudaFuncAttributeMaxDynamicSharedMemorySize, XP_SMEM);
        cudaFuncSetAttribute(gru_persist, cudaFuncAttributeMaxDynamicSharedMemorySize, GR_SMEM);
        attr_set = true;
    }

    proj_split<<<BT, 128>>>(actions, fc_w, fc_b);
    split_w<<<2 * G3H, 256>>>(w_ih, w_hh);
    split_h0<<<Bdim, 256>>>(hidden);
    xp_mma<<<dim3(32, 256), 256, XP_SMEM>>>(b_ih);
    gru_persist<<<dim3(32, 4), 512, GR_SMEM>>>(hidden, b_hh, out);
}

// round 12
// speedup vs baseline: 1.2501x; 1.2501x over previous
#include <cuda_runtime.h>
#include <cuda_bf16.h>
#include <math.h>
#include <stdint.h>

#define Bdim 128
#define Tdim 256
#define Adim 8
#define Hdim 1024
#define BT   (Bdim * Tdim)        // 32768
#define G3H  (3 * Hdim)           // 3072
#define KC   3072                 // concat K (xp gemm only)
#define KC2  2048                 // [h1|h2] / [w1|w2] width (gru)
#define NCH  48                   // K chunks of 64 (xp gemm)
#define GCH  16                   // 64-K super-chunks (gru)

// ---------------- device scratch ----------------
__device__ float g_xp[(size_t)BT * G3H];                 // [BT,3H] fp32
__device__ __nv_bfloat16 g_Axp[(size_t)BT * KC];         // [x1|x1|x2] (xp)
__device__ __nv_bfloat16 g_Bih[(size_t)G3H * KC];        // row n: [w1|w2|w1] (xp)
__device__ __nv_bfloat16 g_Bhh[(size_t)G3H * KC2];       // row j=3i+g: [w1|w2]
__device__ __nv_bfloat16 g_Ah[2][(size_t)Bdim * KC2];    // [h1|h2] ping-pong
__device__ unsigned g_bar_count;
__device__ unsigned g_bar_flag;

// ---------------- helpers ----------------
__device__ __forceinline__ uint32_t smem_to_u32(const void* p) {
    uint32_t a;
    asm("{ .reg .u64 t; cvta.to.shared.u64 t, %1; cvt.u32.u64 %0, t; }" : "=r"(a) : "l"(p));
    return a;
}
__device__ __forceinline__ void ldsm4(uint32_t* r, uint32_t a) {
    asm volatile("ldmatrix.sync.aligned.m8n8.x4.shared.b16 {%0,%1,%2,%3}, [%4];"
        : "=r"(r[0]), "=r"(r[1]), "=r"(r[2]), "=r"(r[3]) : "r"(a));
}
__device__ __forceinline__ void mma16816(float* d, const uint32_t* a, const uint32_t* b) {
    asm volatile("mma.sync.aligned.m16n8k16.row.col.f32.bf16.bf16.f32 "
        "{%0,%1,%2,%3}, {%4,%5,%6,%7}, {%8,%9}, {%0,%1,%2,%3};"
        : "+f"(d[0]), "+f"(d[1]), "+f"(d[2]), "+f"(d[3])
        : "r"(a[0]), "r"(a[1]), "r"(a[2]), "r"(a[3]), "r"(b[0]), "r"(b[1]));
}
#define CP_ASYNC16(d, s) asm volatile("cp.async.cg.shared.global [%0], [%1], 16;" :: "r"(d), "l"(s))
#define CP_COMMIT()      asm volatile("cp.async.commit_group;" ::: "memory")
#define CP_WAIT2()       asm volatile("cp.async.wait_group 2;" ::: "memory")
#define CP_WAIT4()       asm volatile("cp.async.wait_group 4;" ::: "memory")
#define CP_WAIT_ALL()    asm volatile("cp.async.wait_group 0;" ::: "memory")
#define SWZ(o) ((o) ^ (((o) >> 3) & 0x70))

// ---------------- kernel 1: proj + split (xp operand, [x1|x1|x2]) -------
__global__ __launch_bounds__(128) void proj_split(
    const float* __restrict__ actions, const float* __restrict__ fc_w,
    const float* __restrict__ fc_b)
{
    const int m = blockIdx.x, t = threadIdx.x;
    __shared__ float act[Adim];
    if (t < Adim) act[t] = actions[m * Adim + t];
    __syncthreads();
    const float a0 = act[0], a1 = act[1], a2 = act[2], a3 = act[3];
    const float a4 = act[4], a5 = act[5], a6 = act[6], a7 = act[7];
    __nv_bfloat16* dst = g_Axp + (size_t)m * KC;
#pragma unroll
    for (int j = 0; j < Hdim / 128; j++) {
        const int h = t + j * 128;
        const float4* wp = reinterpret_cast<const float4*>(fc_w + (size_t)h * Adim);
        const float4 w0 = wp[0], w1 = wp[1];
        float v = fc_b[h];
        v += a0 * w0.x + a1 * w0.y + a2 * w0.z + a3 * w0.w;
        v += a4 * w1.x + a5 * w1.y + a6 * w1.z + a7 * w1.w;
        v = fmaxf(v, 0.0f);
        const __nv_bfloat16 x1 = __float2bfloat16(v);
        const __nv_bfloat16 x2 = __float2bfloat16(v - __bfloat162float(x1));
        dst[h] = x1; dst[Hdim + h] = x1; dst[2 * Hdim + h] = x2;
    }
}

// ---------------- kernel 2: weight splits -------------------------------
__global__ __launch_bounds__(256) void split_w(
    const float* __restrict__ w_ih, const float* __restrict__ w_hh)
{
    const int bid = blockIdx.x;
    if (bid < G3H) {
        const float* src = w_ih + (size_t)bid * Hdim;
        __nv_bfloat16* dst = g_Bih + (size_t)bid * KC;
#pragma unroll
        for (int u = 0; u < Hdim / 256; u++) {
            const int k = threadIdx.x + u * 256;
            const float w = src[k];
            const __nv_bfloat16 w1 = __float2bfloat16(w);
            const __nv_bfloat16 w2 = __float2bfloat16(w - __bfloat162float(w1));
            dst[k] = w1; dst[Hdim + k] = w2; dst[2 * Hdim + k] = w1;
        }
    } else {
        const int j = bid - G3H, g = j % 3, i = j / 3;
        const float* src = w_hh + (size_t)(g * Hdim + i) * Hdim;
        __nv_bfloat16* dst = g_Bhh + (size_t)j * KC2;
#pragma unroll
        for (int u = 0; u < Hdim / 256; u++) {
            const int k = threadIdx.x + u * 256;
            const float w = src[k];
            const __nv_bfloat16 w1 = __float2bfloat16(w);
            const __nv_bfloat16 w2 = __float2bfloat16(w - __bfloat162float(w1));
            dst[k] = w1; dst[Hdim + k] = w2;
        }
    }
}

// ---------------- kernel 3: split hidden + reset barrier ----------------
__global__ __launch_bounds__(256) void split_h0(const float* __restrict__ hidden)
{
    if (blockIdx.x == 0 && threadIdx.x == 0) { g_bar_count = 0; g_bar_flag = 0; }
    const int b = blockIdx.x;
    __nv_bfloat16* dst = g_Ah[0] + (size_t)b * KC2;
    const float* src = hidden + (size_t)b * Hdim;
#pragma unroll
    for (int u = 0; u < Hdim / 256; u++) {
        const int k = threadIdx.x + u * 256;
        const float h = src[k];
        const __nv_bfloat16 h1 = __float2bfloat16(h);
        const __nv_bfloat16 h2 = __float2bfloat16(h - __bfloat162float(h1));
        dst[k] = h1; dst[Hdim + k] = h2;
    }
}

// ---------------- kernel 4: xp GEMM via mma.sync (proven) ---------------
#define XP_STAGE 28672
#define XP_SMEM  (4 * XP_STAGE)

__global__ __launch_bounds__(256) void xp_mma(const float* __restrict__ b_ih)
{
    extern __shared__ char sm[];
    const uint32_t smb = smem_to_u32(sm);
    const int tid = threadIdx.x, lane = tid & 31, wid = tid >> 5;
    const int nb = blockIdx.x, mb = blockIdx.y;

    uint32_t sdst[7]; const char* gsrc[7];
#pragma unroll
    for (int u = 0; u < 7; u++) {
        const int sidx = tid + u * 256;
        if (sidx < 1024) {
            const int row = sidx >> 3, s8 = sidx & 7;
            sdst[u] = SWZ((uint32_t)(row * 128 + s8 * 16));
            gsrc[u] = (const char*)g_Axp + (size_t)(mb * 128 + row) * (KC * 2) + s8 * 16;
        } else {
            const int bx = sidx - 1024, row = bx >> 3, s8 = bx & 7;
            sdst[u] = 16384u + SWZ((uint32_t)(row * 128 + s8 * 16));
            gsrc[u] = (const char*)g_Bih + (size_t)(nb * 96 + row) * (KC * 2) + s8 * 16;
        }
    }
    auto prefetch = [&](int c) {
        if (c < NCH) {
            const uint32_t sb = smb + (uint32_t)(c & 3) * XP_STAGE;
            const size_t off = (size_t)c * 128;
#pragma unroll
            for (int u = 0; u < 7; u++) CP_ASYNC16(sb + sdst[u], gsrc[u] + off);
        }
        CP_COMMIT();
    };

    const int mrow0 = (wid & 3) * 32, nc0 = (wid >> 2) * 48;
    const uint32_t ar0 = mrow0 + (lane & 15), ar1 = ar0 + 16;
    const uint32_t aoff0 = ar0 * 128, amk0 = (ar0 & 7) << 4;
    const uint32_t aoff1 = ar1 * 128, amk1 = (ar1 & 7) << 4;
    const uint32_t akh = (uint32_t)(lane >> 4) * 16;
    uint32_t boff[3], bmk[3];
#pragma unroll
    for (int p = 0; p < 3; p++) {
        const uint32_t nr = nc0 + p * 16 + (lane >> 4) * 8 + (lane & 7);
        boff[p] = 16384u + nr * 128; bmk[p] = (nr & 7) << 4;
    }
    const uint32_t bkh = (uint32_t)((lane >> 3) & 1) * 16;

    float acc[2][6][4] = {};
    prefetch(0); prefetch(1); prefetch(2);
    for (int c = 0; c < NCH; c++) {
        CP_WAIT2();
        __syncthreads();
        prefetch(c + 3);
        const uint32_t sb = smb + (uint32_t)(c & 3) * XP_STAGE;
#pragma unroll
        for (int s = 0; s < 4; s++) {
            uint32_t a0[4], a1[4], b[12];
            const uint32_t cA = akh + s * 32, cB = bkh + s * 32;
            ldsm4(a0, sb + aoff0 + (cA ^ amk0));
            ldsm4(a1, sb + aoff1 + (cA ^ amk1));
#pragma unroll
            for (int p = 0; p < 3; p++) ldsm4(b + 4 * p, sb + boff[p] + (cB ^ bmk[p]));
#pragma unroll
            for (int nt = 0; nt < 6; nt++) {
                mma16816(acc[0][nt], a0, b + 2 * nt);
                mma16816(acc[1][nt], a1, b + 2 * nt);
            }
        }
    }

    const int q = lane & 3, r4 = lane >> 2;
#pragma unroll
    for (int mg = 0; mg < 2; mg++) {
        const int row = mb * 128 + mrow0 + mg * 16 + r4;
#pragma unroll
        for (int nt = 0; nt < 6; nt++) {
            const int col = nb * 96 + nc0 + nt * 8 + 2 * q;
            const float2 bias = *reinterpret_cast<const float2*>(b_ih + col);
            float2 v0, v1;
            v0.x = acc[mg][nt][0] + bias.x; v0.y = acc[mg][nt][1] + bias.y;
            v1.x = acc[mg][nt][2] + bias.x; v1.y = acc[mg][nt][3] + bias.y;
            *reinterpret_cast<float2*>(g_xp + (size_t)row * G3H + col) = v0;
            *reinterpret_cast<float2*>(g_xp + (size_t)(row + 8) * G3H + col) = v1;
        }
    }
}

// ---------------- kernel 5: persistent GRU, shared-slice products -------
// 128 CTAs (nb 0..31, mb 0..3), 512 thr. Tile 32x96 over h-K=1024 in 16
// super-chunks of 64. acc += H1*W1 + H1*W2 + H2*W1 (slices loaded once).
// Stage (32KB): A_h1@0 (4KB) | A_h2@4K | B_w1@8K (12KB) | B_w2@20K.
// 6-stage ring. 12 k16-steps/chunk split 3-per-warp-group (4-way s-split).
#define GR_STAGE 32768
#define GR_NST   6
#define GR_SMEM  (GR_NST * GR_STAGE)
#define NBLK 128

__global__ __launch_bounds__(512) void gru_persist(
    const float* __restrict__ hidden,
    const float* __restrict__ b_hh, float* __restrict__ out)
{
    extern __shared__ char sm[];
    const uint32_t smb = smem_to_u32(sm);
    const int tid = threadIdx.x, lane = tid & 31, wid = tid >> 5;
    const int kw = wid >> 2;                  // 0..3: s-step triple
    const int q  = wid & 3;                   // quad within group
    const int nb = blockIdx.x, mb = blockIdx.y;
    const int b0 = mb * 32, i0 = nb * 32;

    // ---- step-invariant load addresses: 1 A seg + 3 B segs per thread ----
    uint32_t sdstA; size_t aoffA;
    uint32_t sdstB[3]; const char* bsrcB[3];
    {
        const int hA = tid >> 8, r = (tid & 255) >> 3, s8 = tid & 7;
        sdstA = (uint32_t)(hA * 4096) + SWZ((uint32_t)(r * 128 + s8 * 16));
        aoffA = (size_t)(b0 + r) * (KC2 * 2) + hA * (Hdim * 2) + s8 * 16;
    }
#pragma unroll
    for (int u = 0; u < 3; u++) {
        const int bx = tid + u * 512;         // 0..1535
        const int hB = bx >= 768, rb = (bx - hB * 768) >> 3, s8 = bx & 7;
        sdstB[u] = (uint32_t)(8192 + hB * 12288) + SWZ((uint32_t)(rb * 128 + s8 * 16));
        bsrcB[u] = (const char*)g_Bhh + (size_t)(nb * 96 + rb) * (KC2 * 2) + hB * (Hdim * 2) + s8 * 16;
    }

    const int mrow0 = (q & 1) * 16, nc0 = (q >> 1) * 48;
    const uint32_t ar = mrow0 + (lane & 15);
    const uint32_t aoff = ar * 128, amk = (ar & 7) << 4;
    const uint32_t akh = (uint32_t)(lane >> 4) * 16;
    uint32_t boff[3], bmk[3];
#pragma unroll
    for (int p = 0; p < 3; p++) {
        const uint32_t nr = nc0 + p * 16 + (lane >> 4) * 8 + (lane & 7);
        boff[p] = nr * 128; bmk[p] = (nr & 7) << 4;
    }
    const uint32_t bkh = (uint32_t)((lane >> 3) & 1) * 16;

    // ---- step-invariant epilogue state: h and biases in regs ----
    float hv[2], bh0[2], bh1[2], bh2[2];
#pragma unroll
    for (int u = 0; u < 2; u++) {
        const int idx = tid + u * 512;
        const int b = b0 + (idx >> 5), i = i0 + (idx & 31);
        hv[u]  = hidden[(size_t)b * Hdim + i];
        bh0[u] = b_hh[i]; bh1[u] = b_hh[Hdim + i]; bh2[u] = b_hh[2 * Hdim + i];
    }

    for (int t = 0; t < Tdim; t++) {
        const char* Ab = (const char*)g_Ah[t & 1];
        float acc[6][4] = {};

        auto prefetch = [&](int c, int st) {
            if (c < GCH) {
                const uint32_t sb = smb + (uint32_t)st * GR_STAGE;
                const size_t off = (size_t)c * 128;
                CP_ASYNC16(sb + sdstA, Ab + aoffA + off);
#pragma unroll
                for (int u = 0; u < 3; u++) CP_ASYNC16(sb + sdstB[u], bsrcB[u] + off);
            }
            CP_COMMIT();
        };

#pragma unroll
        for (int c = 0; c < 5; c++) prefetch(c, c);

        int sc = 0;
        for (int c = 0; c < GCH; c++) {
            CP_WAIT4();
            __syncthreads();
            {
                int sp = sc + 5; if (sp >= GR_NST) sp -= GR_NST;
                prefetch(c + 5, sp);
            }
            const uint32_t sb = smb + (uint32_t)sc * GR_STAGE;
#pragma unroll
            for (int s2 = 0; s2 < 3; s2++) {
                const int s = kw * 3 + s2;                // 0..11
                const int p = s >> 2, sk = s & 3;         // product, k16 index
                const uint32_t aR = (p == 2) ? 4096u : 0u;
                const uint32_t bR = 8192u + ((p == 1) ? 12288u : 0u);
                uint32_t a[4], b[12];
                const uint32_t cA = akh + sk * 32, cB = bkh + sk * 32;
                ldsm4(a, sb + aR + aoff + (cA ^ amk));
#pragma unroll
                for (int pq = 0; pq < 3; pq++)
                    ldsm4(b + 4 * pq, sb + bR + boff[pq] + (cB ^ bmk[pq]));
#pragma unroll
                for (int nt = 0; nt < 6; nt++) mma16816(acc[nt], a, b + 2 * nt);
            }
            sc++; if (sc == GR_NST) sc = 0;
        }
        CP_WAIT_ALL();

        // hoisted xp loads (latency hidden under the smem reduce)
        float xr[2], xz[2], xn[2];
#pragma unroll
        for (int u = 0; u < 2; u++) {
            const int idx = tid + u * 512;
            const int b = b0 + (idx >> 5), i = i0 + (idx & 31);
            const float* xpr = g_xp + ((size_t)b * Tdim + t) * G3H;
            xr[u] = xpr[i]; xz[u] = xpr[Hdim + i]; xn[u] = xpr[2 * Hdim + i];
        }

        // ---- reduce the four partials via smem ----
        float* hp = reinterpret_cast<float*>(sm);  // 4 x [32][100] fp32
        __syncthreads();
        {
            float* hpk = hp + kw * 3200;
            const int q4 = lane & 3, r0 = mrow0 + (lane >> 2);
#pragma unroll
            for (int nt = 0; nt < 6; nt++) {
                const int cc = nc0 + nt * 8 + 2 * q4;
                hpk[r0 * 100 + cc]           = acc[nt][0];
                hpk[r0 * 100 + cc + 1]       = acc[nt][1];
                hpk[(r0 + 8) * 100 + cc]     = acc[nt][2];
                hpk[(r0 + 8) * 100 + cc + 1] = acc[nt][3];
            }
        }
        __syncthreads();

        __nv_bfloat16* Abase = g_Ah[(t & 1) ^ 1];
#pragma unroll
        for (int u = 0; u < 2; u++) {
            const int idx = tid + u * 512;
            const int bl = idx >> 5, il = idx & 31;
            const int b = b0 + bl, i = i0 + il;
            const int o = bl * 100 + 3 * il;
            const float hr = hp[o + 0] + hp[3200 + o + 0] + hp[6400 + o + 0] + hp[9600 + o + 0] + bh0[u];
            const float hz = hp[o + 1] + hp[3200 + o + 1] + hp[6400 + o + 1] + hp[9600 + o + 1] + bh1[u];
            const float hn = hp[o + 2] + hp[3200 + o + 2] + hp[6400 + o + 2] + hp[9600 + o + 2] + bh2[u];
            const float rg = 1.0f / (1.0f + expf(-(xr[u] + hr)));
            const float zg = 1.0f / (1.0f + expf(-(xz[u] + hz)));
            const float ng = tanhf(xn[u] + rg * hn);
            const float hnew = (1.0f - zg) * ng + zg * hv[u];
            hv[u] = hnew;
            out[((size_t)b * Tdim + t) * Hdim + i] = hnew;
            const __nv_bfloat16 h1 = __float2bfloat16(hnew);
            const __nv_bfloat16 h2 = __float2bfloat16(hnew - __bfloat162float(h1));
            __nv_bfloat16* An = Abase + (size_t)b * KC2;
            An[i] = h1; An[Hdim + i] = h2;
        }

        // ---- device-wide barrier ----
        __syncthreads();
        if (tid == 0) {
            __threadfence();
            const unsigned prev = atomicAdd(&g_bar_count, 1u);
            if (prev == NBLK - 1) {
                g_bar_count = 0;
                __threadfence();
                atomicExch(&g_bar_flag, (unsigned)(t + 1));
            } else {
                while (atomicAdd(&g_bar_flag, 0u) < (unsigned)(t + 1))
                    __nanosleep(64);
            }
            __threadfence();
        }
        __syncthreads();
    }
}

// ---------------------------------------------------------------------------
extern "C" void kernel_launch(void* const* d_in, const int* in_sizes, int n_in,
                              void* d_out, int out_size)
{
    const float* actions = (const float*)d_in[0];
    const float* hidden  = (const float*)d_in[1];
    const float* fc_w    = (const float*)d_in[2];
    const float* fc_b    = (const float*)d_in[3];
    const float* w_ih    = (const float*)d_in[4];
    const float* w_hh    = (const float*)d_in[5];
    const float* b_ih    = (const float*)d_in[6];
    const float* b_hh    = (const float*)d_in[7];
    float* out = (float*)d_out;

    static bool attr_set = false;
    if (!attr_set) {
        cudaFuncSetAttribute(xp_mma, cudaFuncAttributeMaxDynamicSharedMemorySize, XP_SMEM);
        cudaFuncSetAttribute(gru_persist, cudaFuncAttributeMaxDynamicSharedMemorySize, GR_SMEM);
        attr_set = true;
    }

    proj_split<<<BT, 128>>>(actions, fc_w, fc_b);
    split_w<<<2 * G3H, 256>>>(w_ih, w_hh);
    split_h0<<<Bdim, 256>>>(hidden);
    xp_mma<<<dim3(32, 256), 256, XP_SMEM>>>(b_ih);
    gru_persist<<<dim3(32, 4), 512, GR_SMEM>>>(hidden, b_hh, out);
}

// round 15
// speedup vs baseline: 1.2956x; 1.0364x over previous
#include <cuda_runtime.h>
#include <cuda_bf16.h>
#include <math.h>
#include <stdint.h>

#define Bdim 128
#define Tdim 256
#define Adim 8
#define Hdim 1024
#define BT   (Bdim * Tdim)        // 32768
#define G3H  (3 * Hdim)           // 3072
#define KC   3072                 // concat K (xp gemm only)
#define KC2  2048                 // [h1|h2] / [w1|w2] width (gru)
#define NCH  48                   // K chunks of 64 (xp gemm)
#define GCH  16                   // 64-K super-chunks (gru)

// ---------------- device scratch ----------------
__device__ float g_xp[(size_t)BT * G3H];                 // [BT,3H] fp32
__device__ __nv_bfloat16 g_Axp[(size_t)BT * KC];         // [x1|x1|x2] (xp)
__device__ __nv_bfloat16 g_Bih[(size_t)G3H * KC];        // row n: [w1|w2|w1] (xp)
__device__ __nv_bfloat16 g_Bhh[(size_t)G3H * KC2];       // row j=3i+g: [w1|w2]
__device__ __nv_bfloat16 g_Ah[2][(size_t)Bdim * KC2];    // [h1|h2] ping-pong
__device__ unsigned g_cnt4[4];                           // per-mb barrier counts
__device__ unsigned g_flag4[4];                          // per-mb barrier flags

// ---------------- helpers ----------------
__device__ __forceinline__ uint32_t smem_to_u32(const void* p) {
    uint32_t a;
    asm("{ .reg .u64 t; cvta.to.shared.u64 t, %1; cvt.u32.u64 %0, t; }" : "=r"(a) : "l"(p));
    return a;
}
__device__ __forceinline__ void ldsm4(uint32_t* r, uint32_t a) {
    asm volatile("ldmatrix.sync.aligned.m8n8.x4.shared.b16 {%0,%1,%2,%3}, [%4];"
        : "=r"(r[0]), "=r"(r[1]), "=r"(r[2]), "=r"(r[3]) : "r"(a));
}
__device__ __forceinline__ void mma16816(float* d, const uint32_t* a, const uint32_t* b) {
    asm volatile("mma.sync.aligned.m16n8k16.row.col.f32.bf16.bf16.f32 "
        "{%0,%1,%2,%3}, {%4,%5,%6,%7}, {%8,%9}, {%0,%1,%2,%3};"
        : "+f"(d[0]), "+f"(d[1]), "+f"(d[2]), "+f"(d[3])
        : "r"(a[0]), "r"(a[1]), "r"(a[2]), "r"(a[3]), "r"(b[0]), "r"(b[1]));
}
#define CP_ASYNC16(d, s) asm volatile("cp.async.cg.shared.global [%0], [%1], 16;" :: "r"(d), "l"(s))
#define CP_COMMIT()      asm volatile("cp.async.commit_group;" ::: "memory")
#define CP_WAIT2()       asm volatile("cp.async.wait_group 2;" ::: "memory")
#define CP_WAIT4()       asm volatile("cp.async.wait_group 4;" ::: "memory")
#define CP_WAIT_ALL()    asm volatile("cp.async.wait_group 0;" ::: "memory")
#define SWZ(o) ((o) ^ (((o) >> 3) & 0x70))

// ---------------- kernel 1: proj + split (xp operand, [x1|x1|x2]) -------
__global__ __launch_bounds__(128) void proj_split(
    const float* __restrict__ actions, const float* __restrict__ fc_w,
    const float* __restrict__ fc_b)
{
    const int m = blockIdx.x, t = threadIdx.x;
    __shared__ float act[Adim];
    if (t < Adim) act[t] = actions[m * Adim + t];
    __syncthreads();
    const float a0 = act[0], a1 = act[1], a2 = act[2], a3 = act[3];
    const float a4 = act[4], a5 = act[5], a6 = act[6], a7 = act[7];
    __nv_bfloat16* dst = g_Axp + (size_t)m * KC;
#pragma unroll
    for (int j = 0; j < Hdim / 128; j++) {
        const int h = t + j * 128;
        const float4* wp = reinterpret_cast<const float4*>(fc_w + (size_t)h * Adim);
        const float4 w0 = wp[0], w1 = wp[1];
        float v = fc_b[h];
        v += a0 * w0.x + a1 * w0.y + a2 * w0.z + a3 * w0.w;
        v += a4 * w1.x + a5 * w1.y + a6 * w1.z + a7 * w1.w;
        v = fmaxf(v, 0.0f);
        const __nv_bfloat16 x1 = __float2bfloat16(v);
        const __nv_bfloat16 x2 = __float2bfloat16(v - __bfloat162float(x1));
        dst[h] = x1; dst[Hdim + h] = x1; dst[2 * Hdim + h] = x2;
    }
}

// ---------------- kernel 2: weight splits -------------------------------
__global__ __launch_bounds__(256) void split_w(
    const float* __restrict__ w_ih, const float* __restrict__ w_hh)
{
    const int bid = blockIdx.x;
    if (bid < G3H) {
        const float* src = w_ih + (size_t)bid * Hdim;
        __nv_bfloat16* dst = g_Bih + (size_t)bid * KC;
#pragma unroll
        for (int u = 0; u < Hdim / 256; u++) {
            const int k = threadIdx.x + u * 256;
            const float w = src[k];
            const __nv_bfloat16 w1 = __float2bfloat16(w);
            const __nv_bfloat16 w2 = __float2bfloat16(w - __bfloat162float(w1));
            dst[k] = w1; dst[Hdim + k] = w2; dst[2 * Hdim + k] = w1;
        }
    } else {
        const int j = bid - G3H, g = j % 3, i = j / 3;
        const float* src = w_hh + (size_t)(g * Hdim + i) * Hdim;
        __nv_bfloat16* dst = g_Bhh + (size_t)j * KC2;
#pragma unroll
        for (int u = 0; u < Hdim / 256; u++) {
            const int k = threadIdx.x + u * 256;
            const float w = src[k];
            const __nv_bfloat16 w1 = __float2bfloat16(w);
            const __nv_bfloat16 w2 = __float2bfloat16(w - __bfloat162float(w1));
            dst[k] = w1; dst[Hdim + k] = w2;
        }
    }
}

// ---------------- kernel 3: split hidden + reset barriers ---------------
__global__ __launch_bounds__(256) void split_h0(const float* __restrict__ hidden)
{
    if (blockIdx.x == 0 && threadIdx.x < 4) {
        g_cnt4[threadIdx.x] = 0; g_flag4[threadIdx.x] = 0;
    }
    const int b = blockIdx.x;
    __nv_bfloat16* dst = g_Ah[0] + (size_t)b * KC2;
    const float* src = hidden + (size_t)b * Hdim;
#pragma unroll
    for (int u = 0; u < Hdim / 256; u++) {
        const int k = threadIdx.x + u * 256;
        const float h = src[k];
        const __nv_bfloat16 h1 = __float2bfloat16(h);
        const __nv_bfloat16 h2 = __float2bfloat16(h - __bfloat162float(h1));
        dst[k] = h1; dst[Hdim + k] = h2;
    }
}

// ---------------- kernel 4: xp GEMM via mma.sync (proven) ---------------
#define XP_STAGE 28672
#define XP_SMEM  (4 * XP_STAGE)

__global__ __launch_bounds__(256) void xp_mma(const float* __restrict__ b_ih)
{
    extern __shared__ char sm[];
    const uint32_t smb = smem_to_u32(sm);
    const int tid = threadIdx.x, lane = tid & 31, wid = tid >> 5;
    const int nb = blockIdx.x, mb = blockIdx.y;

    uint32_t sdst[7]; const char* gsrc[7];
#pragma unroll
    for (int u = 0; u < 7; u++) {
        const int sidx = tid + u * 256;
        if (sidx < 1024) {
            const int row = sidx >> 3, s8 = sidx & 7;
            sdst[u] = SWZ((uint32_t)(row * 128 + s8 * 16));
            gsrc[u] = (const char*)g_Axp + (size_t)(mb * 128 + row) * (KC * 2) + s8 * 16;
        } else {
            const int bx = sidx - 1024, row = bx >> 3, s8 = bx & 7;
            sdst[u] = 16384u + SWZ((uint32_t)(row * 128 + s8 * 16));
            gsrc[u] = (const char*)g_Bih + (size_t)(nb * 96 + row) * (KC * 2) + s8 * 16;
        }
    }
    auto prefetch = [&](int c) {
        if (c < NCH) {
            const uint32_t sb = smb + (uint32_t)(c & 3) * XP_STAGE;
            const size_t off = (size_t)c * 128;
#pragma unroll
            for (int u = 0; u < 7; u++) CP_ASYNC16(sb + sdst[u], gsrc[u] + off);
        }
        CP_COMMIT();
    };

    const int mrow0 = (wid & 3) * 32, nc0 = (wid >> 2) * 48;
    const uint32_t ar0 = mrow0 + (lane & 15), ar1 = ar0 + 16;
    const uint32_t aoff0 = ar0 * 128, amk0 = (ar0 & 7) << 4;
    const uint32_t aoff1 = ar1 * 128, amk1 = (ar1 & 7) << 4;
    const uint32_t akh = (uint32_t)(lane >> 4) * 16;
    uint32_t boff[3], bmk[3];
#pragma unroll
    for (int p = 0; p < 3; p++) {
        const uint32_t nr = nc0 + p * 16 + (lane >> 4) * 8 + (lane & 7);
        boff[p] = 16384u + nr * 128; bmk[p] = (nr & 7) << 4;
    }
    const uint32_t bkh = (uint32_t)((lane >> 3) & 1) * 16;

    float acc[2][6][4] = {};
    prefetch(0); prefetch(1); prefetch(2);
    for (int c = 0; c < NCH; c++) {
        CP_WAIT2();
        __syncthreads();
        prefetch(c + 3);
        const uint32_t sb = smb + (uint32_t)(c & 3) * XP_STAGE;
#pragma unroll
        for (int s = 0; s < 4; s++) {
            uint32_t a0[4], a1[4], b[12];
            const uint32_t cA = akh + s * 32, cB = bkh + s * 32;
            ldsm4(a0, sb + aoff0 + (cA ^ amk0));
            ldsm4(a1, sb + aoff1 + (cA ^ amk1));
#pragma unroll
            for (int p = 0; p < 3; p++) ldsm4(b + 4 * p, sb + boff[p] + (cB ^ bmk[p]));
#pragma unroll
            for (int nt = 0; nt < 6; nt++) {
                mma16816(acc[0][nt], a0, b + 2 * nt);
                mma16816(acc[1][nt], a1, b + 2 * nt);
            }
        }
    }

    const int q = lane & 3, r4 = lane >> 2;
#pragma unroll
    for (int mg = 0; mg < 2; mg++) {
        const int row = mb * 128 + mrow0 + mg * 16 + r4;
#pragma unroll
        for (int nt = 0; nt < 6; nt++) {
            const int col = nb * 96 + nc0 + nt * 8 + 2 * q;
            const float2 bias = *reinterpret_cast<const float2*>(b_ih + col);
            float2 v0, v1;
            v0.x = acc[mg][nt][0] + bias.x; v0.y = acc[mg][nt][1] + bias.y;
            v1.x = acc[mg][nt][2] + bias.x; v1.y = acc[mg][nt][3] + bias.y;
            *reinterpret_cast<float2*>(g_xp + (size_t)row * G3H + col) = v0;
            *reinterpret_cast<float2*>(g_xp + (size_t)(row + 8) * G3H + col) = v1;
        }
    }
}

// ---------------- kernel 5: persistent GRU, shared-slice products -------
// 128 CTAs (nb 0..31, mb 0..3), 512 thr. Tile 32x96 over h-K=1024 in 16
// super-chunks of 64. acc += H1*W1 + H1*W2 + H2*W1 (slices loaded once).
// Stage (32KB): A_h1@0 (4KB) | A_h2@4K | B_w1@8K (12KB) | B_w2@20K.
// 6-stage ring. PER-MB barriers: 4 independent 32-CTA groups (dependency
// graph is block-diagonal in mb). xp epilogue loads hoisted to step start.
#define GR_STAGE 32768
#define GR_NST   6
#define GR_SMEM  (GR_NST * GR_STAGE)
#define GRP 32                                  // CTAs per barrier group

__global__ __launch_bounds__(512) void gru_persist(
    const float* __restrict__ hidden,
    const float* __restrict__ b_hh, float* __restrict__ out)
{
    extern __shared__ char sm[];
    const uint32_t smb = smem_to_u32(sm);
    const int tid = threadIdx.x, lane = tid & 31, wid = tid >> 5;
    const int kw = wid >> 2;                  // 0..3: s-step triple
    const int q  = wid & 3;                   // quad within group
    const int nb = blockIdx.x, mb = blockIdx.y;
    const int b0 = mb * 32, i0 = nb * 32;

    // ---- step-invariant load addresses: 1 A seg + 3 B segs per thread ----
    uint32_t sdstA; size_t aoffA;
    uint32_t sdstB[3]; const char* bsrcB[3];
    {
        const int hA = tid >> 8, r = (tid & 255) >> 3, s8 = tid & 7;
        sdstA = (uint32_t)(hA * 4096) + SWZ((uint32_t)(r * 128 + s8 * 16));
        aoffA = (size_t)(b0 + r) * (KC2 * 2) + hA * (Hdim * 2) + s8 * 16;
    }
#pragma unroll
    for (int u = 0; u < 3; u++) {
        const int bx = tid + u * 512;         // 0..1535
        const int hB = bx >= 768, rb = (bx - hB * 768) >> 3, s8 = bx & 7;
        sdstB[u] = (uint32_t)(8192 + hB * 12288) + SWZ((uint32_t)(rb * 128 + s8 * 16));
        bsrcB[u] = (const char*)g_Bhh + (size_t)(nb * 96 + rb) * (KC2 * 2) + hB * (Hdim * 2) + s8 * 16;
    }

    const int mrow0 = (q & 1) * 16, nc0 = (q >> 1) * 48;
    const uint32_t ar = mrow0 + (lane & 15);
    const uint32_t aoff = ar * 128, amk = (ar & 7) << 4;
    const uint32_t akh = (uint32_t)(lane >> 4) * 16;
    uint32_t boff[3], bmk[3];
#pragma unroll
    for (int p = 0; p < 3; p++) {
        const uint32_t nr = nc0 + p * 16 + (lane >> 4) * 8 + (lane & 7);
        boff[p] = nr * 128; bmk[p] = (nr & 7) << 4;
    }
    const uint32_t bkh = (uint32_t)((lane >> 3) & 1) * 16;

    // ---- step-invariant epilogue state: h and biases in regs ----
    float hv[2], bh0[2], bh1[2], bh2[2];
#pragma unroll
    for (int u = 0; u < 2; u++) {
        const int idx = tid + u * 512;
        const int b = b0 + (idx >> 5), i = i0 + (idx & 31);
        hv[u]  = hidden[(size_t)b * Hdim + i];
        bh0[u] = b_hh[i]; bh1[u] = b_hh[Hdim + i]; bh2[u] = b_hh[2 * Hdim + i];
    }

    for (int t = 0; t < Tdim; t++) {
        const char* Ab = (const char*)g_Ah[t & 1];
        float acc[6][4] = {};

        // hoisted xp loads — issued at step start, latency hidden by mainloop
        float xr[2], xz[2], xn[2];
#pragma unroll
        for (int u = 0; u < 2; u++) {
            const int idx = tid + u * 512;
            const int b = b0 + (idx >> 5), i = i0 + (idx & 31);
            const float* xpr = g_xp + ((size_t)b * Tdim + t) * G3H;
            xr[u] = xpr[i]; xz[u] = xpr[Hdim + i]; xn[u] = xpr[2 * Hdim + i];
        }

        auto prefetch = [&](int c, int st) {
            if (c < GCH) {
                const uint32_t sb = smb + (uint32_t)st * GR_STAGE;
                const size_t off = (size_t)c * 128;
                CP_ASYNC16(sb + sdstA, Ab + aoffA + off);
#pragma unroll
                for (int u = 0; u < 3; u++) CP_ASYNC16(sb + sdstB[u], bsrcB[u] + off);
            }
            CP_COMMIT();
        };

#pragma unroll
        for (int c = 0; c < 5; c++) prefetch(c, c);

        int sc = 0;
        for (int c = 0; c < GCH; c++) {
            CP_WAIT4();
            __syncthreads();
            {
                int sp = sc + 5; if (sp >= GR_NST) sp -= GR_NST;
                prefetch(c + 5, sp);
            }
            const uint32_t sb = smb + (uint32_t)sc * GR_STAGE;
#pragma unroll
            for (int s2 = 0; s2 < 3; s2++) {
                const int s = kw * 3 + s2;                // 0..11
                const int p = s >> 2, sk = s & 3;         // product, k16 index
                const uint32_t aR = (p == 2) ? 4096u : 0u;
                const uint32_t bR = 8192u + ((p == 1) ? 12288u : 0u);
                uint32_t a[4], b[12];
                const uint32_t cA = akh + sk * 32, cB = bkh + sk * 32;
                ldsm4(a, sb + aR + aoff + (cA ^ amk));
#pragma unroll
                for (int pq = 0; pq < 3; pq++)
                    ldsm4(b + 4 * pq, sb + bR + boff[pq] + (cB ^ bmk[pq]));
#pragma unroll
                for (int nt = 0; nt < 6; nt++) mma16816(acc[nt], a, b + 2 * nt);
            }
            sc++; if (sc == GR_NST) sc = 0;
        }
        CP_WAIT_ALL();

        // ---- reduce the four partials via smem ----
        float* hp = reinterpret_cast<float*>(sm);  // 4 x [32][100] fp32
        __syncthreads();
        {
            float* hpk = hp + kw * 3200;
            const int q4 = lane & 3, r0 = mrow0 + (lane >> 2);
#pragma unroll
            for (int nt = 0; nt < 6; nt++) {
                const int cc = nc0 + nt * 8 + 2 * q4;
                hpk[r0 * 100 + cc]           = acc[nt][0];
                hpk[r0 * 100 + cc + 1]       = acc[nt][1];
                hpk[(r0 + 8) * 100 + cc]     = acc[nt][2];
                hpk[(r0 + 8) * 100 + cc + 1] = acc[nt][3];
            }
        }
        __syncthreads();

        __nv_bfloat16* Abase = g_Ah[(t & 1) ^ 1];
#pragma unroll
        for (int u = 0; u < 2; u++) {
            const int idx = tid + u * 512;
            const int bl = idx >> 5, il = idx & 31;
            const int b = b0 + bl, i = i0 + il;
            const int o = bl * 100 + 3 * il;
            const float hr = hp[o + 0] + hp[3200 + o + 0] + hp[6400 + o + 0] + hp[9600 + o + 0] + bh0[u];
            const float hz = hp[o + 1] + hp[3200 + o + 1] + hp[6400 + o + 1] + hp[9600 + o + 1] + bh1[u];
            const float hn = hp[o + 2] + hp[3200 + o + 2] + hp[6400 + o + 2] + hp[9600 + o + 2] + bh2[u];
            const float rg = 1.0f / (1.0f + expf(-(xr[u] + hr)));
            const float zg = 1.0f / (1.0f + expf(-(xz[u] + hz)));
            const float ng = tanhf(xn[u] + rg * hn);
            const float hnew = (1.0f - zg) * ng + zg * hv[u];
            hv[u] = hnew;
            out[((size_t)b * Tdim + t) * Hdim + i] = hnew;
            const __nv_bfloat16 h1 = __float2bfloat16(hnew);
            const __nv_bfloat16 h2 = __float2bfloat16(hnew - __bfloat162float(h1));
            __nv_bfloat16* An = Abase + (size_t)b * KC2;
            An[i] = h1; An[Hdim + i] = h2;
        }

        // ---- per-mb-group barrier (32 CTAs) ----
        __syncthreads();
        if (tid == 0) {
            __threadfence();
            const unsigned prev = atomicAdd(&g_cnt4[mb], 1u);
            if (prev == GRP - 1) {
                g_cnt4[mb] = 0;
                __threadfence();
                atomicExch(&g_flag4[mb], (unsigned)(t + 1));
            } else {
                while (atomicAdd(&g_flag4[mb], 0u) < (unsigned)(t + 1))
                    __nanosleep(32);
            }
            __threadfence();
        }
        __syncthreads();
    }
}

// ---------------------------------------------------------------------------
extern "C" void kernel_launch(void* const* d_in, const int* in_sizes, int n_in,
                              void* d_out, int out_size)
{
    const float* actions = (const float*)d_in[0];
    const float* hidden  = (const float*)d_in[1];
    const float* fc_w    = (const float*)d_in[2];
    const float* fc_b    = (const float*)d_in[3];
    const float* w_ih    = (const float*)d_in[4];
    const float* w_hh    = (const float*)d_in[5];
    const float* b_ih    = (const float*)d_in[6];
    const float* b_hh    = (const float*)d_in[7];
    float* out = (float*)d_out;

    static bool attr_set = false;
    if (!attr_set) {
        cudaFuncSetAttribute(xp_mma, cudaFuncAttributeMaxDynamicSharedMemorySize, XP_SMEM);
        cudaFuncSetAttribute(gru_persist, cudaFuncAttributeMaxDynamicSharedMemorySize, GR_SMEM);
        attr_set = true;
    }

    proj_split<<<BT, 128>>>(actions, fc_w, fc_b);
    split_w<<<2 * G3H, 256>>>(w_ih, w_hh);
    split_h0<<<Bdim, 256>>>(hidden);
    xp_mma<<<dim3(32, 256), 256, XP_SMEM>>>(b_ih);
    gru_persist<<<dim3(32, 4), 512, GR_SMEM>>>(hidden, b_hh, out);
}

// round 16
// speedup vs baseline: 1.2972x; 1.0012x over previous
#include <cuda_runtime.h>
#include <cuda_bf16.h>
#include <math.h>
#include <stdint.h>

#define Bdim 128
#define Tdim 256
#define Adim 8
#define Hdim 1024
#define BT   (Bdim * Tdim)        // 32768
#define G3H  (3 * Hdim)           // 3072
#define KC   3072                 // concat K (xp gemm only)
#define KC2  2048                 // [h1|h2] / [w1|w2] width (gru)
#define NCH  48                   // K chunks of 64 (xp gemm)
#define GCH  16                   // 64-K super-chunks (gru)

// ---------------- device scratch ----------------
__device__ float g_xp[(size_t)BT * G3H];                 // [BT,3H] fp32
__device__ __nv_bfloat16 g_Axp[(size_t)BT * KC];         // [x1|x1|x2] (xp)
__device__ __nv_bfloat16 g_Bih[(size_t)G3H * KC];        // row n: [w1|w2|w1] (xp)
__device__ __nv_bfloat16 g_Bhh[(size_t)G3H * KC2];       // row j=3i+g: [w1|w2]
__device__ __nv_bfloat16 g_Ah[2][(size_t)Bdim * KC2];    // [h1|h2] ping-pong
__device__ unsigned g_cnt4[4];                           // per-mb barrier counts
__device__ unsigned g_flag4[4];                          // per-mb barrier flags

// ---------------- helpers ----------------
__device__ __forceinline__ uint32_t smem_to_u32(const void* p) {
    uint32_t a;
    asm("{ .reg .u64 t; cvta.to.shared.u64 t, %1; cvt.u32.u64 %0, t; }" : "=r"(a) : "l"(p));
    return a;
}
__device__ __forceinline__ void ldsm4(uint32_t* r, uint32_t a) {
    asm volatile("ldmatrix.sync.aligned.m8n8.x4.shared.b16 {%0,%1,%2,%3}, [%4];"
        : "=r"(r[0]), "=r"(r[1]), "=r"(r[2]), "=r"(r[3]) : "r"(a));
}
__device__ __forceinline__ void mma16816(float* d, const uint32_t* a, const uint32_t* b) {
    asm volatile("mma.sync.aligned.m16n8k16.row.col.f32.bf16.bf16.f32 "
        "{%0,%1,%2,%3}, {%4,%5,%6,%7}, {%8,%9}, {%0,%1,%2,%3};"
        : "+f"(d[0]), "+f"(d[1]), "+f"(d[2]), "+f"(d[3])
        : "r"(a[0]), "r"(a[1]), "r"(a[2]), "r"(a[3]), "r"(b[0]), "r"(b[1]));
}
#define CP_ASYNC16(d, s) asm volatile("cp.async.cg.shared.global [%0], [%1], 16;" :: "r"(d), "l"(s))
#define CP_COMMIT()      asm volatile("cp.async.commit_group;" ::: "memory")
#define CP_WAIT1()       asm volatile("cp.async.wait_group 1;" ::: "memory")
#define CP_WAIT4()       asm volatile("cp.async.wait_group 4;" ::: "memory")
#define CP_WAIT_ALL()    asm volatile("cp.async.wait_group 0;" ::: "memory")
#define SWZ(o) ((o) ^ (((o) >> 3) & 0x70))

// ---------------- kernel 1: proj + split (xp operand, [x1|x1|x2]) -------
__global__ __launch_bounds__(128) void proj_split(
    const float* __restrict__ actions, const float* __restrict__ fc_w,
    const float* __restrict__ fc_b)
{
    const int m = blockIdx.x, t = threadIdx.x;
    __shared__ float act[Adim];
    if (t < Adim) act[t] = actions[m * Adim + t];
    __syncthreads();
    const float a0 = act[0], a1 = act[1], a2 = act[2], a3 = act[3];
    const float a4 = act[4], a5 = act[5], a6 = act[6], a7 = act[7];
    __nv_bfloat16* dst = g_Axp + (size_t)m * KC;
#pragma unroll
    for (int j = 0; j < Hdim / 128; j++) {
        const int h = t + j * 128;
        const float4* wp = reinterpret_cast<const float4*>(fc_w + (size_t)h * Adim);
        const float4 w0 = wp[0], w1 = wp[1];
        float v = fc_b[h];
        v += a0 * w0.x + a1 * w0.y + a2 * w0.z + a3 * w0.w;
        v += a4 * w1.x + a5 * w1.y + a6 * w1.z + a7 * w1.w;
        v = fmaxf(v, 0.0f);
        const __nv_bfloat16 x1 = __float2bfloat16(v);
        const __nv_bfloat16 x2 = __float2bfloat16(v - __bfloat162float(x1));
        dst[h] = x1; dst[Hdim + h] = x1; dst[2 * Hdim + h] = x2;
    }
}

// ---------------- kernel 2: weight splits -------------------------------
__global__ __launch_bounds__(256) void split_w(
    const float* __restrict__ w_ih, const float* __restrict__ w_hh)
{
    const int bid = blockIdx.x;
    if (bid < G3H) {
        const float* src = w_ih + (size_t)bid * Hdim;
        __nv_bfloat16* dst = g_Bih + (size_t)bid * KC;
#pragma unroll
        for (int u = 0; u < Hdim / 256; u++) {
            const int k = threadIdx.x + u * 256;
            const float w = src[k];
            const __nv_bfloat16 w1 = __float2bfloat16(w);
            const __nv_bfloat16 w2 = __float2bfloat16(w - __bfloat162float(w1));
            dst[k] = w1; dst[Hdim + k] = w2; dst[2 * Hdim + k] = w1;
        }
    } else {
        const int j = bid - G3H, g = j % 3, i = j / 3;
        const float* src = w_hh + (size_t)(g * Hdim + i) * Hdim;
        __nv_bfloat16* dst = g_Bhh + (size_t)j * KC2;
#pragma unroll
        for (int u = 0; u < Hdim / 256; u++) {
            const int k = threadIdx.x + u * 256;
            const float w = src[k];
            const __nv_bfloat16 w1 = __float2bfloat16(w);
            const __nv_bfloat16 w2 = __float2bfloat16(w - __bfloat162float(w1));
            dst[k] = w1; dst[Hdim + k] = w2;
        }
    }
}

// ---------------- kernel 3: split hidden + reset barriers ---------------
__global__ __launch_bounds__(256) void split_h0(const float* __restrict__ hidden)
{
    if (blockIdx.x == 0 && threadIdx.x < 4) {
        g_cnt4[threadIdx.x] = 0; g_flag4[threadIdx.x] = 0;
    }
    const int b = blockIdx.x;
    __nv_bfloat16* dst = g_Ah[0] + (size_t)b * KC2;
    const float* src = hidden + (size_t)b * Hdim;
#pragma unroll
    for (int u = 0; u < Hdim / 256; u++) {
        const int k = threadIdx.x + u * 256;
        const float h = src[k];
        const __nv_bfloat16 h1 = __float2bfloat16(h);
        const __nv_bfloat16 h2 = __float2bfloat16(h - __bfloat162float(h1));
        dst[k] = h1; dst[Hdim + k] = h2;
    }
}

// ---------------- kernel 4: xp GEMM, 3 stages -> 2 CTAs/SM --------------
#define XP_STAGE 28672
#define XP_NST   3
#define XP_SMEM  (XP_NST * XP_STAGE)

__global__ __launch_bounds__(256, 2) void xp_mma(const float* __restrict__ b_ih)
{
    extern __shared__ char sm[];
    const uint32_t smb = smem_to_u32(sm);
    const int tid = threadIdx.x, lane = tid & 31, wid = tid >> 5;
    const int nb = blockIdx.x, mb = blockIdx.y;

    uint32_t sdst[7]; const char* gsrc[7];
#pragma unroll
    for (int u = 0; u < 7; u++) {
        const int sidx = tid + u * 256;
        if (sidx < 1024) {
            const int row = sidx >> 3, s8 = sidx & 7;
            sdst[u] = SWZ((uint32_t)(row * 128 + s8 * 16));
            gsrc[u] = (const char*)g_Axp + (size_t)(mb * 128 + row) * (KC * 2) + s8 * 16;
        } else {
            const int bx = sidx - 1024, row = bx >> 3, s8 = bx & 7;
            sdst[u] = 16384u + SWZ((uint32_t)(row * 128 + s8 * 16));
            gsrc[u] = (const char*)g_Bih + (size_t)(nb * 96 + row) * (KC * 2) + s8 * 16;
        }
    }
    auto prefetch = [&](int c, int st) {
        if (c < NCH) {
            const uint32_t sb = smb + (uint32_t)st * XP_STAGE;
            const size_t off = (size_t)c * 128;
#pragma unroll
            for (int u = 0; u < 7; u++) CP_ASYNC16(sb + sdst[u], gsrc[u] + off);
        }
        CP_COMMIT();
    };

    const int mrow0 = (wid & 3) * 32, nc0 = (wid >> 2) * 48;
    const uint32_t ar0 = mrow0 + (lane & 15), ar1 = ar0 + 16;
    const uint32_t aoff0 = ar0 * 128, amk0 = (ar0 & 7) << 4;
    const uint32_t aoff1 = ar1 * 128, amk1 = (ar1 & 7) << 4;
    const uint32_t akh = (uint32_t)(lane >> 4) * 16;
    uint32_t boff[3], bmk[3];
#pragma unroll
    for (int p = 0; p < 3; p++) {
        const uint32_t nr = nc0 + p * 16 + (lane >> 4) * 8 + (lane & 7);
        boff[p] = 16384u + nr * 128; bmk[p] = (nr & 7) << 4;
    }
    const uint32_t bkh = (uint32_t)((lane >> 3) & 1) * 16;

    float acc[2][6][4] = {};
    prefetch(0, 0); prefetch(1, 1);
    int sc = 0;
    for (int c = 0; c < NCH; c++) {
        CP_WAIT1();
        __syncthreads();
        {
            int sp = sc + 2; if (sp >= XP_NST) sp -= XP_NST;
            prefetch(c + 2, sp);
        }
        const uint32_t sb = smb + (uint32_t)sc * XP_STAGE;
#pragma unroll
        for (int s = 0; s < 4; s++) {
            uint32_t a0[4], a1[4], b[12];
            const uint32_t cA = akh + s * 32, cB = bkh + s * 32;
            ldsm4(a0, sb + aoff0 + (cA ^ amk0));
            ldsm4(a1, sb + aoff1 + (cA ^ amk1));
#pragma unroll
            for (int p = 0; p < 3; p++) ldsm4(b + 4 * p, sb + boff[p] + (cB ^ bmk[p]));
#pragma unroll
            for (int nt = 0; nt < 6; nt++) {
                mma16816(acc[0][nt], a0, b + 2 * nt);
                mma16816(acc[1][nt], a1, b + 2 * nt);
            }
        }
        sc++; if (sc == XP_NST) sc = 0;
    }

    const int q = lane & 3, r4 = lane >> 2;
#pragma unroll
    for (int mg = 0; mg < 2; mg++) {
        const int row = mb * 128 + mrow0 + mg * 16 + r4;
#pragma unroll
        for (int nt = 0; nt < 6; nt++) {
            const int col = nb * 96 + nc0 + nt * 8 + 2 * q;
            const float2 bias = *reinterpret_cast<const float2*>(b_ih + col);
            float2 v0, v1;
            v0.x = acc[mg][nt][0] + bias.x; v0.y = acc[mg][nt][1] + bias.y;
            v1.x = acc[mg][nt][2] + bias.x; v1.y = acc[mg][nt][3] + bias.y;
            *reinterpret_cast<float2*>(g_xp + (size_t)row * G3H + col) = v0;
            *reinterpret_cast<float2*>(g_xp + (size_t)(row + 8) * G3H + col) = v1;
        }
    }
}

// ---------------- kernel 5: persistent GRU, shared-slice products -------
// 128 CTAs (nb 0..31, mb 0..3), 512 thr. Tile 32x96 over h-K=1024 in 16
// super-chunks of 64. acc += H1*W1 + H1*W2 + H2*W1 (slices loaded once).
// Stage (32KB): A_h1@0 (4KB) | A_h2@4K | B_w1@8K (12KB) | B_w2@20K. 6-stage
// ring. Step tail: An stores -> arrive -> pre-issue next B fill + out
// stores (overlap barrier wait) -> wait -> A fills. Group 0 of each step =
// {B0..B4, A0}; chunk-c readiness under wait_group 4 unchanged.
#define GR_STAGE 32768
#define GR_NST   6
#define GR_SMEM  (GR_NST * GR_STAGE)
#define GRP 32                                  // CTAs per barrier group

__global__ __launch_bounds__(512) void gru_persist(
    const float* __restrict__ hidden,
    const float* __restrict__ b_hh, float* __restrict__ out)
{
    extern __shared__ char sm[];
    const uint32_t smb = smem_to_u32(sm);
    const int tid = threadIdx.x, lane = tid & 31, wid = tid >> 5;
    const int kw = wid >> 2;                  // 0..3: s-step triple
    const int q  = wid & 3;                   // quad within group
    const int nb = blockIdx.x, mb = blockIdx.y;
    const int b0 = mb * 32, i0 = nb * 32;

    // ---- step-invariant load addresses: 1 A seg + 3 B segs per thread ----
    uint32_t sdstA; size_t aoffA;
    uint32_t sdstB[3]; const char* bsrcB[3];
    {
        const int hA = tid >> 8, r = (tid & 255) >> 3, s8 = tid & 7;
        sdstA = (uint32_t)(hA * 4096) + SWZ((uint32_t)(r * 128 + s8 * 16));
        aoffA = (size_t)(b0 + r) * (KC2 * 2) + hA * (Hdim * 2) + s8 * 16;
    }
#pragma unroll
    for (int u = 0; u < 3; u++) {
        const int bx = tid + u * 512;         // 0..1535
        const int hB = bx >= 768, rb = (bx - hB * 768) >> 3, s8 = bx & 7;
        sdstB[u] = (uint32_t)(8192 + hB * 12288) + SWZ((uint32_t)(rb * 128 + s8 * 16));
        bsrcB[u] = (const char*)g_Bhh + (size_t)(nb * 96 + rb) * (KC2 * 2) + hB * (Hdim * 2) + s8 * 16;
    }

    const int mrow0 = (q & 1) * 16, nc0 = (q >> 1) * 48;
    const uint32_t ar = mrow0 + (lane & 15);
    const uint32_t aoff = ar * 128, amk = (ar & 7) << 4;
    const uint32_t akh = (uint32_t)(lane >> 4) * 16;
    uint32_t boff[3], bmk[3];
#pragma unroll
    for (int p = 0; p < 3; p++) {
        const uint32_t nr = nc0 + p * 16 + (lane >> 4) * 8 + (lane & 7);
        boff[p] = nr * 128; bmk[p] = (nr & 7) << 4;
    }
    const uint32_t bkh = (uint32_t)((lane >> 3) & 1) * 16;

    // ---- step-invariant epilogue state: h and biases in regs ----
    float hv[2], bh0[2], bh1[2], bh2[2];
#pragma unroll
    for (int u = 0; u < 2; u++) {
        const int idx = tid + u * 512;
        const int b = b0 + (idx >> 5), i = i0 + (idx & 31);
        hv[u]  = hidden[(size_t)b * Hdim + i];
        bh0[u] = b_hh[i]; bh1[u] = b_hh[Hdim + i]; bh2[u] = b_hh[2 * Hdim + i];
    }

    auto issueB5 = [&]() {   // B parts of chunks 0..4 (uncommitted)
#pragma unroll
        for (int c = 0; c < 5; c++) {
            const uint32_t sb = smb + (uint32_t)c * GR_STAGE;
            const size_t off = (size_t)c * 128;
#pragma unroll
            for (int u = 0; u < 3; u++) CP_ASYNC16(sb + sdstB[u], bsrcB[u] + off);
        }
    };

    issueB5();   // step 0 pre-fill (g_Ah[0] ready by stream order)

    for (int t = 0; t < Tdim; t++) {
        const char* Ab = (const char*)g_Ah[t & 1];
        float acc[6][4] = {};

        // hoisted xp loads — latency hidden by fill + mainloop
        float xr[2], xz[2], xn[2];
#pragma unroll
        for (int u = 0; u < 2; u++) {
            const int idx = tid + u * 512;
            const int b = b0 + (idx >> 5), i = i0 + (idx & 31);
            const float* xpr = g_xp + ((size_t)b * Tdim + t) * G3H;
            xr[u] = xpr[i]; xz[u] = xpr[Hdim + i]; xn[u] = xpr[2 * Hdim + i];
        }

        // A fills + commits (B parts of chunks 0-4 already in flight)
#pragma unroll
        for (int c = 0; c < 5; c++) {
            const uint32_t sb = smb + (uint32_t)c * GR_STAGE;
            CP_ASYNC16(sb + sdstA, Ab + aoffA + (size_t)c * 128);
            CP_COMMIT();
        }

        int sc = 0;
        for (int c = 0; c < GCH; c++) {
            CP_WAIT4();
            __syncthreads();
            {
                const int cp = c + 5;
                if (cp < GCH) {
                    int sp = sc + 5; if (sp >= GR_NST) sp -= GR_NST;
                    const uint32_t sb = smb + (uint32_t)sp * GR_STAGE;
                    const size_t off = (size_t)cp * 128;
                    CP_ASYNC16(sb + sdstA, Ab + aoffA + off);
#pragma unroll
                    for (int u = 0; u < 3; u++) CP_ASYNC16(sb + sdstB[u], bsrcB[u] + off);
                }
                CP_COMMIT();
            }
            const uint32_t sb = smb + (uint32_t)sc * GR_STAGE;
#pragma unroll
            for (int s2 = 0; s2 < 3; s2++) {
                const int s = kw * 3 + s2;                // 0..11
                const int p = s >> 2, sk = s & 3;         // product, k16 index
                const uint32_t aR = (p == 2) ? 4096u : 0u;
                const uint32_t bR = 8192u + ((p == 1) ? 12288u : 0u);
                uint32_t a[4], b[12];
                const uint32_t cA = akh + sk * 32, cB = bkh + sk * 32;
                ldsm4(a, sb + aR + aoff + (cA ^ amk));
#pragma unroll
                for (int pq = 0; pq < 3; pq++)
                    ldsm4(b + 4 * pq, sb + bR + boff[pq] + (cB ^ bmk[pq]));
#pragma unroll
                for (int nt = 0; nt < 6; nt++) mma16816(acc[nt], a, b + 2 * nt);
            }
            sc++; if (sc == GR_NST) sc = 0;
        }
        CP_WAIT_ALL();

        // ---- reduce the four partials via smem ----
        float* hp = reinterpret_cast<float*>(sm);  // 4 x [32][100] fp32
        __syncthreads();
        {
            float* hpk = hp + kw * 3200;
            const int q4 = lane & 3, r0 = mrow0 + (lane >> 2);
#pragma unroll
            for (int nt = 0; nt < 6; nt++) {
                const int cc = nc0 + nt * 8 + 2 * q4;
                hpk[r0 * 100 + cc]           = acc[nt][0];
                hpk[r0 * 100 + cc + 1]       = acc[nt][1];
                hpk[(r0 + 8) * 100 + cc]     = acc[nt][2];
                hpk[(r0 + 8) * 100 + cc + 1] = acc[nt][3];
            }
        }
        __syncthreads();

        // ---- gates; write An (next-step operand) FIRST ----
        float hnew[2];
        __nv_bfloat16* Abase = g_Ah[(t & 1) ^ 1];
#pragma unroll
        for (int u = 0; u < 2; u++) {
            const int idx = tid + u * 512;
            const int bl = idx >> 5, il = idx & 31;
            const int b = b0 + bl, i = i0 + il;
            const int o = bl * 100 + 3 * il;
            const float hr = hp[o + 0] + hp[3200 + o + 0] + hp[6400 + o + 0] + hp[9600 + o + 0] + bh0[u];
            const float hz = hp[o + 1] + hp[3200 + o + 1] + hp[6400 + o + 1] + hp[9600 + o + 1] + bh1[u];
            const float hn = hp[o + 2] + hp[3200 + o + 2] + hp[6400 + o + 2] + hp[9600 + o + 2] + bh2[u];
            const float rg = 1.0f / (1.0f + expf(-(xr[u] + hr)));
            const float zg = 1.0f / (1.0f + expf(-(xz[u] + hz)));
            const float ng = tanhf(xn[u] + rg * hn);
            hnew[u] = (1.0f - zg) * ng + zg * hv[u];
            hv[u] = hnew[u];
            const __nv_bfloat16 h1 = __float2bfloat16(hnew[u]);
            const __nv_bfloat16 h2 = __float2bfloat16(hnew[u] - __bfloat162float(h1));
            __nv_bfloat16* An = Abase + (size_t)b * KC2;
            An[i] = h1; An[Hdim + i] = h2;
        }
        __syncthreads();          // all An stores issued (hp reads done too)

        // arrive ASAP
        if (tid == 0) {
            __threadfence();
            const unsigned prev = atomicAdd(&g_cnt4[mb], 1u);
            if (prev == GRP - 1) {
                g_cnt4[mb] = 0;
                __threadfence();
                atomicExch(&g_flag4[mb], (unsigned)(t + 1));
            }
        }

        // overlap barrier wait: next step's B fill + out stores
        if (t + 1 < Tdim) issueB5();
#pragma unroll
        for (int u = 0; u < 2; u++) {
            const int idx = tid + u * 512;
            const int b = b0 + (idx >> 5), i = i0 + (idx & 31);
            out[((size_t)b * Tdim + t) * Hdim + i] = hnew[u];
        }

        // wait for the group's An writes
        if (tid == 0) {
            while (atomicAdd(&g_flag4[mb], 0u) < (unsigned)(t + 1))
                __nanosleep(32);
            __threadfence();
        }
        __syncthreads();
    }
}

// ---------------------------------------------------------------------------
extern "C" void kernel_launch(void* const* d_in, const int* in_sizes, int n_in,
                              void* d_out, int out_size)
{
    const float* actions = (const float*)d_in[0];
    const float* hidden  = (const float*)d_in[1];
    const float* fc_w    = (const float*)d_in[2];
    const float* fc_b    = (const float*)d_in[3];
    const float* w_ih    = (const float*)d_in[4];
    const float* w_hh    = (const float*)d_in[5];
    const float* b_ih    = (const float*)d_in[6];
    const float* b_hh    = (const float*)d_in[7];
    float* out = (float*)d_out;

    static bool attr_set = false;
    if (!attr_set) {
        cudaFuncSetAttribute(xp_mma, cudaFuncAttributeMaxDynamicSharedMemorySize, XP_SMEM);
        cudaFuncSetAttribute(gru_persist, cudaFuncAttributeMaxDynamicSharedMemorySize, GR_SMEM);
        attr_set = true;
    }

    proj_split<<<BT, 128>>>(actions, fc_w, fc_b);
    split_w<<<2 * G3H, 256>>>(w_ih, w_hh);
    split_h0<<<Bdim, 256>>>(hidden);
    xp_mma<<<dim3(32, 256), 256, XP_SMEM>>>(b_ih);
    gru_persist<<<dim3(32, 4), 512, GR_SMEM>>>(hidden, b_hh, out);
}